// round 11
// baseline (speedup 1.0000x reference)
#include <cuda_runtime.h>
#include <cuda_fp16.h>
#include <mma.h>
#include <cstdint>

using namespace nvcuda;

#define NN 100000
#define NE 1600000
#define PADN 100096   // ceil(NN/64)*64 rounded up past 782*128; pad rows stay zero

// ---------------- scratch (device globals; no allocation allowed) ----------------
__device__ __align__(16) float g_h[(size_t)PADN * 128];              // fp32 hidden (aggr2 gather)
__device__ __align__(16) unsigned short g_ahi[(size_t)PADN * 128];   // aggr out, fp16 hi
__device__ __align__(16) unsigned short g_alo[(size_t)PADN * 128];   // aggr out, fp16 lo
__device__ __align__(16) unsigned short g_xhi[(size_t)PADN * 128];   // x split
__device__ __align__(16) unsigned short g_xlo[(size_t)PADN * 128];
__device__ __align__(16) unsigned short g_hhi[(size_t)PADN * 128];   // h split
__device__ __align__(16) unsigned short g_hlo[(size_t)PADN * 128];
__device__ int g_deg[NN];          // zero at call start (re-zeroed by aggr2)
__device__ int g_rowStart[NN];
__device__ int g_cursor[NN];
__device__ int g_srcIdx[NE];
__device__ int g_ctr;              // zero at call start (re-zeroed by aggr2)
// fp16 weight images: [half][k 0..127][n 0..NP)
__device__ __align__(16) unsigned short g_Bimg1[2 * 128 * 136];  // layer1 NP=136
__device__ __align__(16) unsigned short g_Bimg2[2 * 128 * 72];   // layer2 NP=72

// split one float pair into packed fp16 hi and lo words (hi+lo ~exact to 2^-22)
__device__ __forceinline__ void split2h(float a, float b, uint32_t& h, uint32_t& l) {
    __half2 hb = __floats2half2_rn(a, b);
    float2 hf = __half22float2(hb);
    __half2 lb = __floats2half2_rn(a - hf.x, b - hf.y);
    h = *reinterpret_cast<uint32_t*>(&hb);
    l = *reinterpret_cast<uint32_t*>(&lb);
}

// ---------------- CSR build (3 launches; segments unordered -- max is order-insensitive) ----
__global__ void k_count(const int* __restrict__ edst) {
    int i = blockIdx.x * blockDim.x + threadIdx.x;
    if (i < NE) atomicAdd(&g_deg[edst[i]], 1);
}
__global__ void __launch_bounds__(256) k_offsets() {
    __shared__ int s[256];
    __shared__ int base;
    int t = threadIdx.x;
    int i = blockIdx.x * 256 + t;
    int d = (i < NN) ? g_deg[i] : 0;
    s[t] = d;
    __syncthreads();
#pragma unroll
    for (int off = 1; off < 256; off <<= 1) {
        int x = (t >= off) ? s[t - off] : 0;
        __syncthreads();
        s[t] += x;
        __syncthreads();
    }
    if (t == 255) base = atomicAdd(&g_ctr, s[255]);
    __syncthreads();
    if (i < NN) {
        int r = base + s[t] - d;
        g_rowStart[i] = r;
        g_cursor[i] = r;
    }
}
__global__ void k_fill(const int* __restrict__ esrc, const int* __restrict__ edst) {
    int i = blockIdx.x * blockDim.x + threadIdx.x;
    if (i < NE) {
        int p = atomicAdd(&g_cursor[edst[i]], 1);
        g_srcIdx[p] = esrc[i];
    }
}

// ---------------- x split (streaming, once per call) ----------------
__global__ void k_splitX(const float* __restrict__ x) {
    size_t i = (size_t)blockIdx.x * blockDim.x + threadIdx.x;   // over NN*32 float4s
    if (i >= (size_t)NN * 32) return;
    float4 v = ((const float4*)x)[i];
    uint32_t h0, l0, h1, l1;
    split2h(v.x, v.y, h0, l0);
    split2h(v.z, v.w, h1, l1);
    ((uint2*)g_xhi)[i] = make_uint2(h0, h1);
    ((uint2*)g_xlo)[i] = make_uint2(l0, l1);
}

// ---------------- aggregation: warp per node, gather-max, emit split fp16 ----------------
__device__ __forceinline__ float4 max4(float4 a, float4 b) {
    return make_float4(fmaxf(a.x, b.x), fmaxf(a.y, b.y), fmaxf(a.z, b.z), fmaxf(a.w, b.w));
}
template<bool USE_H, bool ZERO>
__global__ void __launch_bounds__(256) k_aggr(const float* __restrict__ xin) {
    int w = (blockIdx.x * blockDim.x + threadIdx.x) >> 5;
    if (w >= NN) return;
    int lane = threadIdx.x & 31;
    const float* feat = USE_H ? g_h : xin;
    int beg = g_rowStart[w];
    int deg = g_deg[w];
    int end = beg + deg;
    if (ZERO) {                          // restore invariant for next call (after reading deg)
        if (lane == 0) g_deg[w] = 0;
        if (w == 0 && lane == 0) g_ctr = 0;
    }
    const float NEG = __int_as_float(0xff800000);
    float4 m = make_float4(NEG, NEG, NEG, NEG);
    int e = beg;
    for (; e + 4 <= end; e += 4) {
        float4 v0 = *(const float4*)(feat + (size_t)g_srcIdx[e + 0] * 128 + lane * 4);
        float4 v1 = *(const float4*)(feat + (size_t)g_srcIdx[e + 1] * 128 + lane * 4);
        float4 v2 = *(const float4*)(feat + (size_t)g_srcIdx[e + 2] * 128 + lane * 4);
        float4 v3 = *(const float4*)(feat + (size_t)g_srcIdx[e + 3] * 128 + lane * 4);
        m = max4(m, max4(max4(v0, v1), max4(v2, v3)));
    }
    for (; e < end; e++) {
        float4 v0 = *(const float4*)(feat + (size_t)g_srcIdx[e] * 128 + lane * 4);
        m = max4(m, v0);
    }
    if (deg == 0) m = make_float4(0.f, 0.f, 0.f, 0.f);
    uint32_t h0, l0, h1, l1;
    split2h(m.x, m.y, h0, l0);
    split2h(m.z, m.w, h1, l1);
    ((uint2*)g_ahi)[(size_t)w * 32 + lane] = make_uint2(h0, h1);
    ((uint2*)g_alo)[(size_t)w * 32 + lane] = make_uint2(l0, l1);
}

// ---------------- weight prep: single fp16 B[k][n] image per half ----------------
template<int COUT>
__global__ void k_prepB(const float* __restrict__ Wl, const float* __restrict__ Wr,
                        unsigned short* __restrict__ dst) {
    constexpr int NP = COUT + 8;
    int idx = blockIdx.x * blockDim.x + threadIdx.x;
    if (idx >= 2 * 128 * COUT) return;
    int half = idx / (128 * COUT);
    int rem = idx - half * 128 * COUT;
    int k = rem / COUT;
    int n = rem - k * COUT;
    float f = (half ? Wr : Wl)[k * COUT + n];
    __half hb = __float2half_rn(f);
    dst[((size_t)half * 128 + k) * NP + n] = *reinterpret_cast<unsigned short*>(&hb);
}

// ---------------- wmma fp16 2-term fused SAGE GEMM (R10 skeleton, prepacked A) ----------
// CTA = 64 rows x COUT, 8 warps in 2(m) x 4(n), warp tile 32 x COUT/4. 3-4 CTAs/SM.
// A arrives pre-split fp16 hi/lo (staging = pure uint4 copy); B single fp16 image/half.
template<int COUT, bool L1>
__global__ void __launch_bounds__(256) k_gemm_wm(const unsigned short* __restrict__ Rhi,
                                                 const unsigned short* __restrict__ Rlo,
                                                 const unsigned short* __restrict__ Bimg,
                                                 const float* __restrict__ bias,
                                                 float* __restrict__ outp) {
    constexpr int BM = 64;
    constexpr int NP = COUT + 8;
    constexpr int AP = 136;
    constexpr int WN = COUT / 4;            // L1:32, L2:16
    constexpr int NT = WN / 16;             // L1:2,  L2:1
    constexpr int EW = WN + 4;
    extern __shared__ char smem[];
    __half* Ah = (__half*)smem;
    __half* Al = Ah + BM * AP;
    __half* Bs = Al + BM * AP;              // current half image: 128 x NP

    int tid = threadIdx.x, wid = tid >> 5, lane = tid & 31;
    int wm = wid & 1, wn = wid >> 1;
    int rowBase = blockIdx.x * BM;          // +63 <= 100031 < PADN, no bounds needed

    wmma::fragment<wmma::accumulator, 16, 16, 16, float> acc[2][NT];
#pragma unroll
    for (int i = 0; i < 2; i++)
#pragma unroll
        for (int j = 0; j < NT; j++) wmma::fill_fragment(acc[i][j], 0.0f);

    for (int half = 0; half < 2; half++) {
        const unsigned short* Shi = half ? Rhi : g_ahi;
        const unsigned short* Slo = half ? Rlo : g_alo;
        // stage A: 1024 uint4 per image (64 rows x 16), 4 per thread per image
#pragma unroll
        for (int it = 0; it < 4; it++) {
            int q = tid + it * 256;            // 0..1023
            int row = q >> 4, quad = q & 15;
            uint4 vh = ((const uint4*)(Shi + (size_t)rowBase * 128))[q];
            uint4 vl = ((const uint4*)(Slo + (size_t)rowBase * 128))[q];
            *(uint4*)((char*)Ah + (size_t)row * (AP * 2) + quad * 16) = vh;
            *(uint4*)((char*)Al + (size_t)row * (AP * 2) + quad * 16) = vl;
        }
        // stage B: this half's fp16 image
        {
            const uint4* src = (const uint4*)(Bimg + (size_t)half * 128 * NP);
            uint4* dst = (uint4*)Bs;
            const int n4 = 128 * NP * 2 / 16;
            for (int i = tid; i < n4; i += 256) dst[i] = src[i];
        }
        __syncthreads();

#pragma unroll
        for (int ks = 0; ks < 8; ks++) {
            int k0 = ks * 16;
            wmma::fragment<wmma::matrix_a, 16, 16, 16, __half, wmma::row_major> fa_h[2], fa_l[2];
#pragma unroll
            for (int mt = 0; mt < 2; mt++) {
                wmma::load_matrix_sync(fa_h[mt], Ah + (size_t)(wm * 32 + mt * 16) * AP + k0, AP);
                wmma::load_matrix_sync(fa_l[mt], Al + (size_t)(wm * 32 + mt * 16) * AP + k0, AP);
            }
#pragma unroll
            for (int nt = 0; nt < NT; nt++) {
                wmma::fragment<wmma::matrix_b, 16, 16, 16, __half, wmma::row_major> fb;
                wmma::load_matrix_sync(fb, Bs + (size_t)k0 * NP + wn * WN + nt * 16, NP);
#pragma unroll
                for (int mt = 0; mt < 2; mt++) wmma::mma_sync(acc[mt][nt], fa_h[mt], fb, acc[mt][nt]);
#pragma unroll
                for (int mt = 0; mt < 2; mt++) wmma::mma_sync(acc[mt][nt], fa_l[mt], fb, acc[mt][nt]);
            }
        }
        __syncthreads();
    }

    // ---- epilogue: bounce fragments through smem, fuse bias+ReLU; L1 also emits split h ----
    float* bw = (float*)Ah + (size_t)wid * 32 * EW;
#pragma unroll
    for (int mt = 0; mt < 2; mt++)
#pragma unroll
        for (int nt = 0; nt < NT; nt++)
            wmma::store_matrix_sync(bw + mt * 16 * EW + nt * 16, acc[mt][nt], EW, wmma::mem_row_major);
    __syncwarp();

    int orow = rowBase + wm * 32 + lane;
    if (orow < NN) {
        const float* br = bw + (size_t)lane * EW;
        int cbase = wn * WN;
#pragma unroll
        for (int c = 0; c < WN; c += 4) {
            float4 v = make_float4(br[c], br[c + 1], br[c + 2], br[c + 3]);
            v.x += bias[cbase + c + 0];
            v.y += bias[cbase + c + 1];
            v.z += bias[cbase + c + 2];
            v.w += bias[cbase + c + 3];
            if (L1) {
                v.x = fmaxf(v.x, 0.f); v.y = fmaxf(v.y, 0.f);
                v.z = fmaxf(v.z, 0.f); v.w = fmaxf(v.w, 0.f);
                size_t o = (size_t)orow * 128 + cbase + c;
                *(float4*)(g_h + o) = v;
                uint32_t h0, l0, h1, l1;
                split2h(v.x, v.y, h0, l0);
                split2h(v.z, v.w, h1, l1);
                *(uint2*)(g_hhi + o) = make_uint2(h0, h1);
                *(uint2*)(g_hlo + o) = make_uint2(l0, l1);
            } else {
                *(float4*)(outp + (size_t)orow * COUT + cbase + c) = v;
            }
        }
    }
}

extern "C" void kernel_launch(void* const* d_in, const int* in_sizes, int n_in,
                              void* d_out, int out_size) {
    const float* x   = (const float*)d_in[0];
    const int*   ei  = (const int*)d_in[1];
    const float* W1l = (const float*)d_in[2];
    const float* b1  = (const float*)d_in[3];
    const float* W1r = (const float*)d_in[4];
    const float* W2l = (const float*)d_in[5];
    const float* b2  = (const float*)d_in[6];
    const float* W2r = (const float*)d_in[7];
    float*       out = (float*)d_out;

    const int* esrc = ei;
    const int* edst = ei + NE;

    const int edgeBlocks  = (NE + 255) / 256;
    const int nodeBlocks  = (NN + 255) / 256;
    const int aggrBlocks  = (NN * 32 + 255) / 256;
    const int splitBlocks = (NN * 32 + 255) / 256;
    const int gemmBlocks  = (NN + 63) / 64;             // 1563

    // dynamic SMEM: A(2 x 64 x 136) + B(128 x NP), fp16  -- same as winning R10
    const int SMEM1 = (2 * 64 * 136 + 128 * 136) * 2;   // 69,632 -> 3 CTAs/SM
    const int SMEM2 = (2 * 64 * 136 + 128 * 72) * 2;    // 53,248 -> 4 CTAs/SM
    cudaFuncSetAttribute(k_gemm_wm<128, true>, cudaFuncAttributeMaxDynamicSharedMemorySize, SMEM1);
    cudaFuncSetAttribute(k_gemm_wm<64, false>, cudaFuncAttributeMaxDynamicSharedMemorySize, SMEM2);

    unsigned short *bimg1, *bimg2, *xhi, *xlo, *hhi, *hlo;
    cudaGetSymbolAddress((void**)&bimg1, g_Bimg1);
    cudaGetSymbolAddress((void**)&bimg2, g_Bimg2);
    cudaGetSymbolAddress((void**)&xhi, g_xhi);
    cudaGetSymbolAddress((void**)&xlo, g_xlo);
    cudaGetSymbolAddress((void**)&hhi, g_hhi);
    cudaGetSymbolAddress((void**)&hlo, g_hlo);

    // CSR build (g_deg / g_ctr zero: zero-init at load + re-zeroed by aggr2 each call)
    k_count<<<edgeBlocks, 256>>>(edst);                                        // 1
    k_offsets<<<nodeBlocks, 256>>>();                                          // 2
    k_fill<<<edgeBlocks, 256>>>(esrc, edst);                                   // 3

    // Layer 1 aggregation -- launch slot 4 (ncu sample)
    k_aggr<false, false><<<aggrBlocks, 256>>>(x);                              // 4

    // independent prep
    k_splitX<<<splitBlocks, 256>>>(x);                                         // 5
    k_prepB<128><<<(2 * 128 * 128 + 255) / 256, 256>>>(W1l, W1r, bimg1);       // 6
    k_prepB<64><<<(2 * 128 * 64 + 255) / 256, 256>>>(W2l, W2r, bimg2);         // 7

    // Layer 1 GEMM, layer 2
    k_gemm_wm<128, true><<<gemmBlocks, 256, SMEM1>>>(xhi, xlo, bimg1, b1, nullptr);   // 8
    k_aggr<true, true><<<aggrBlocks, 256>>>(nullptr);                                  // 9 (re-zeroes deg/ctr)
    k_gemm_wm<64, false><<<gemmBlocks, 256, SMEM2>>>(hhi, hlo, bimg2, b2, out);        // 10
}

// round 12
// speedup vs baseline: 1.0355x; 1.0355x over previous
#include <cuda_runtime.h>
#include <cuda_fp16.h>
#include <mma.h>
#include <cstdint>

using namespace nvcuda;

#define NN 100000
#define NE 1600000

// ---------------- scratch (device globals; no allocation allowed) ----------------
__device__ __align__(16) float g_aggr[(size_t)NN * 128];   // max-aggregated features (fp32)
__device__ __align__(16) float g_h[(size_t)NN * 128];      // hidden activations (fp32)
__device__ int g_deg[NN];          // zero at call start (re-zeroed by aggr2)
__device__ int g_rowStart[NN];
__device__ int g_cursor[NN];
__device__ int g_srcIdx[NE];
__device__ int g_ctr;              // zero at call start (re-zeroed by aggr2)
// fp16 weight images: [half][k 0..127][n 0..NP)
__device__ __align__(16) unsigned short g_Bimg1[2 * 128 * 136];  // layer1 NP=136
__device__ __align__(16) unsigned short g_Bimg2[2 * 128 * 72];   // layer2 NP=72

// split one float pair into packed fp16 hi and lo words (hi+lo ~exact to 2^-22)
__device__ __forceinline__ void split2h(float a, float b, uint32_t& h, uint32_t& l) {
    __half2 hb = __floats2half2_rn(a, b);
    float2 hf = __half22float2(hb);
    __half2 lb = __floats2half2_rn(a - hf.x, b - hf.y);
    h = *reinterpret_cast<uint32_t*>(&hb);
    l = *reinterpret_cast<uint32_t*>(&lb);
}

// ---------------- CSR build (3 launches; segments unordered -- max is order-insensitive) ----
__global__ void k_count(const int* __restrict__ edst) {
    int i = blockIdx.x * blockDim.x + threadIdx.x;
    if (i < NE) atomicAdd(&g_deg[edst[i]], 1);
}
__global__ void __launch_bounds__(256) k_offsets() {
    __shared__ int s[256];
    __shared__ int base;
    int t = threadIdx.x;
    int i = blockIdx.x * 256 + t;
    int d = (i < NN) ? g_deg[i] : 0;
    s[t] = d;
    __syncthreads();
#pragma unroll
    for (int off = 1; off < 256; off <<= 1) {
        int x = (t >= off) ? s[t - off] : 0;
        __syncthreads();
        s[t] += x;
        __syncthreads();
    }
    if (t == 255) base = atomicAdd(&g_ctr, s[255]);
    __syncthreads();
    if (i < NN) {
        int r = base + s[t] - d;
        g_rowStart[i] = r;
        g_cursor[i] = r;
    }
}
__global__ void k_fill(const int* __restrict__ esrc, const int* __restrict__ edst) {
    int i = blockIdx.x * blockDim.x + threadIdx.x;
    if (i < NE) {
        int p = atomicAdd(&g_cursor[edst[i]], 1);
        g_srcIdx[p] = esrc[i];
    }
}

// ---------------- aggregation: warp per node, gather-max, fp32 output ----------------
__device__ __forceinline__ float4 max4(float4 a, float4 b) {
    return make_float4(fmaxf(a.x, b.x), fmaxf(a.y, b.y), fmaxf(a.z, b.z), fmaxf(a.w, b.w));
}
template<bool USE_H, bool ZERO>
__global__ void __launch_bounds__(256) k_aggr(const float* __restrict__ xin) {
    int w = (blockIdx.x * blockDim.x + threadIdx.x) >> 5;
    if (w >= NN) return;
    int lane = threadIdx.x & 31;
    const float* feat = USE_H ? g_h : xin;
    int beg = g_rowStart[w];
    int deg = g_deg[w];
    int end = beg + deg;
    if (ZERO) {                          // restore invariant for next call (after reading deg)
        if (lane == 0) g_deg[w] = 0;
        if (w == 0 && lane == 0) g_ctr = 0;
    }
    const float NEG = __int_as_float(0xff800000);
    float4 m = make_float4(NEG, NEG, NEG, NEG);
    int e = beg;
    for (; e + 4 <= end; e += 4) {
        float4 v0 = *(const float4*)(feat + (size_t)g_srcIdx[e + 0] * 128 + lane * 4);
        float4 v1 = *(const float4*)(feat + (size_t)g_srcIdx[e + 1] * 128 + lane * 4);
        float4 v2 = *(const float4*)(feat + (size_t)g_srcIdx[e + 2] * 128 + lane * 4);
        float4 v3 = *(const float4*)(feat + (size_t)g_srcIdx[e + 3] * 128 + lane * 4);
        m = max4(m, max4(max4(v0, v1), max4(v2, v3)));
    }
    for (; e < end; e++) {
        float4 v0 = *(const float4*)(feat + (size_t)g_srcIdx[e] * 128 + lane * 4);
        m = max4(m, v0);
    }
    if (deg == 0) m = make_float4(0.f, 0.f, 0.f, 0.f);
    *(float4*)(g_aggr + (size_t)w * 128 + lane * 4) = m;
}

// ---------------- weight prep: single fp16 B[k][n] image per half ----------------
template<int COUT>
__global__ void k_prepB(const float* __restrict__ Wl, const float* __restrict__ Wr,
                        unsigned short* __restrict__ dst) {
    constexpr int NP = COUT + 8;
    int idx = blockIdx.x * blockDim.x + threadIdx.x;
    if (idx >= 2 * 128 * COUT) return;
    int half = idx / (128 * COUT);
    int rem = idx - half * 128 * COUT;
    int k = rem / COUT;
    int n = rem - k * COUT;
    float f = (half ? Wr : Wl)[k * COUT + n];
    __half hb = __float2half_rn(f);
    dst[((size_t)half * 128 + k) * NP + n] = *reinterpret_cast<unsigned short*>(&hb);
}

// ---------------- wmma fp16 2-term fused SAGE GEMM (exact R10 winner) ----------------
// CTA = 64 rows x COUT, 8 warps in 2(m) x 4(n), warp tile 32 x COUT/4. 3-4 CTAs/SM.
// A split into fp16 hi+lo during staging; B single fp16 image. Terms: AhB + AlB.
template<int COUT, bool L1>
__global__ void __launch_bounds__(256) k_gemm_wm(const float* __restrict__ xin,
                                                 const unsigned short* __restrict__ Bimg,
                                                 const float* __restrict__ bias,
                                                 float* __restrict__ outp) {
    constexpr int BM = 64;
    constexpr int NP = COUT + 8;
    constexpr int AP = 136;
    constexpr int WN = COUT / 4;            // L1:32, L2:16
    constexpr int NT = WN / 16;             // L1:2,  L2:1
    constexpr int EW = WN + 4;
    extern __shared__ char smem[];
    __half* Ah = (__half*)smem;
    __half* Al = Ah + BM * AP;
    __half* Bs = Al + BM * AP;              // current half image: 128 x NP

    int tid = threadIdx.x, wid = tid >> 5, lane = tid & 31;
    int wm = wid & 1, wn = wid >> 1;
    int rowBase = blockIdx.x * BM;

    wmma::fragment<wmma::accumulator, 16, 16, 16, float> acc[2][NT];
#pragma unroll
    for (int i = 0; i < 2; i++)
#pragma unroll
        for (int j = 0; j < NT; j++) wmma::fill_fragment(acc[i][j], 0.0f);

    const float* rootSrc = L1 ? xin : g_h;
    int r = tid >> 2, kq = (tid & 3) << 5;
    int grow = rowBase + r;

    for (int half = 0; half < 2; half++) {
        const float* Asrc = half ? rootSrc : g_aggr;
        // stage A half: thread covers row r, k in [kq, kq+32), split to hi/lo fp16
        const float4* srcv = (grow < NN) ? (const float4*)(Asrc + (size_t)grow * 128 + kq) : nullptr;
#pragma unroll
        for (int i = 0; i < 8; i++) {
            float4 v = srcv ? srcv[i] : make_float4(0.f, 0.f, 0.f, 0.f);
            uint32_t h0, l0, h1, l1;
            split2h(v.x, v.y, h0, l0);
            split2h(v.z, v.w, h1, l1);
            *(uint2*)((unsigned short*)Ah + (size_t)r * AP + kq + i * 4) = make_uint2(h0, h1);
            *(uint2*)((unsigned short*)Al + (size_t)r * AP + kq + i * 4) = make_uint2(l0, l1);
        }
        // stage B half: copy this half's single fp16 image
        {
            const uint4* src = (const uint4*)(Bimg + (size_t)half * 128 * NP);
            uint4* dst = (uint4*)Bs;
            const int n4 = 128 * NP * 2 / 16;
            for (int i = tid; i < n4; i += 256) dst[i] = src[i];
        }
        __syncthreads();

#pragma unroll
        for (int ks = 0; ks < 8; ks++) {
            int k0 = ks * 16;
            wmma::fragment<wmma::matrix_a, 16, 16, 16, __half, wmma::row_major> fa_h[2], fa_l[2];
#pragma unroll
            for (int mt = 0; mt < 2; mt++) {
                wmma::load_matrix_sync(fa_h[mt], Ah + (size_t)(wm * 32 + mt * 16) * AP + k0, AP);
                wmma::load_matrix_sync(fa_l[mt], Al + (size_t)(wm * 32 + mt * 16) * AP + k0, AP);
            }
#pragma unroll
            for (int nt = 0; nt < NT; nt++) {
                wmma::fragment<wmma::matrix_b, 16, 16, 16, __half, wmma::row_major> fb;
                wmma::load_matrix_sync(fb, Bs + (size_t)k0 * NP + wn * WN + nt * 16, NP);
#pragma unroll
                for (int mt = 0; mt < 2; mt++) wmma::mma_sync(acc[mt][nt], fa_h[mt], fb, acc[mt][nt]);
#pragma unroll
                for (int mt = 0; mt < 2; mt++) wmma::mma_sync(acc[mt][nt], fa_l[mt], fb, acc[mt][nt]);
            }
        }
        __syncthreads();
    }

    // ---- epilogue: bounce fragments through smem, fuse bias+ReLU ----
    float* bw = (float*)Ah + (size_t)wid * 32 * EW;
#pragma unroll
    for (int mt = 0; mt < 2; mt++)
#pragma unroll
        for (int nt = 0; nt < NT; nt++)
            wmma::store_matrix_sync(bw + mt * 16 * EW + nt * 16, acc[mt][nt], EW, wmma::mem_row_major);
    __syncwarp();

    int orow = rowBase + wm * 32 + lane;
    float* out = L1 ? g_h : outp;
    if (orow < NN) {
        float* op = out + (size_t)orow * COUT + wn * WN;
        const float* br = bw + (size_t)lane * EW;
#pragma unroll
        for (int c = 0; c < WN; c += 4) {
            float4 v = make_float4(br[c], br[c + 1], br[c + 2], br[c + 3]);
            v.x += bias[wn * WN + c + 0];
            v.y += bias[wn * WN + c + 1];
            v.z += bias[wn * WN + c + 2];
            v.w += bias[wn * WN + c + 3];
            if (L1) {
                v.x = fmaxf(v.x, 0.f); v.y = fmaxf(v.y, 0.f);
                v.z = fmaxf(v.z, 0.f); v.w = fmaxf(v.w, 0.f);
            }
            *(float4*)(op + c) = v;
        }
    }
}

extern "C" void kernel_launch(void* const* d_in, const int* in_sizes, int n_in,
                              void* d_out, int out_size) {
    const float* x   = (const float*)d_in[0];
    const int*   ei  = (const int*)d_in[1];
    const float* W1l = (const float*)d_in[2];
    const float* b1  = (const float*)d_in[3];
    const float* W1r = (const float*)d_in[4];
    const float* W2l = (const float*)d_in[5];
    const float* b2  = (const float*)d_in[6];
    const float* W2r = (const float*)d_in[7];
    float*       out = (float*)d_out;

    const int* esrc = ei;
    const int* edst = ei + NE;

    const int edgeBlocks = (NE + 255) / 256;
    const int nodeBlocks = (NN + 255) / 256;
    const int aggrBlocks = (NN * 32 + 255) / 256;
    const int gemmBlocks = (NN + 63) / 64;              // 1563

    // dynamic SMEM: A(2 x 64 x 136) + B(128 x NP), fp16  -- same as winning R10
    const int SMEM1 = (2 * 64 * 136 + 128 * 136) * 2;   // 69,632 -> 3 CTAs/SM
    const int SMEM2 = (2 * 64 * 136 + 128 * 72) * 2;    // 53,248 -> 4 CTAs/SM
    cudaFuncSetAttribute(k_gemm_wm<128, true>, cudaFuncAttributeMaxDynamicSharedMemorySize, SMEM1);
    cudaFuncSetAttribute(k_gemm_wm<64, false>, cudaFuncAttributeMaxDynamicSharedMemorySize, SMEM2);

    unsigned short *bimg1, *bimg2;
    cudaGetSymbolAddress((void**)&bimg1, g_Bimg1);
    cudaGetSymbolAddress((void**)&bimg2, g_Bimg2);

    // CSR build (g_deg / g_ctr zero: zero-init at load + re-zeroed by aggr2 each call)
    k_count<<<edgeBlocks, 256>>>(edst);                                        // 1
    k_offsets<<<nodeBlocks, 256>>>();                                          // 2
    k_fill<<<edgeBlocks, 256>>>(esrc, edst);                                   // 3

    // Layer 1 aggregation -- launch slot 4 (ncu sample)
    k_aggr<false, false><<<aggrBlocks, 256>>>(x);                              // 4

    // weight prep
    k_prepB<128><<<(2 * 128 * 128 + 255) / 256, 256>>>(W1l, W1r, bimg1);       // 5
    k_prepB<64><<<(2 * 128 * 64 + 255) / 256, 256>>>(W2l, W2r, bimg2);         // 6

    // Layer 1 GEMM, layer 2
    k_gemm_wm<128, true><<<gemmBlocks, 256, SMEM1>>>(x, bimg1, b1, nullptr);   // 7
    k_aggr<true, true><<<aggrBlocks, 256>>>(nullptr);                           // 8 (re-zeroes deg/ctr)
    k_gemm_wm<64, false><<<gemmBlocks, 256, SMEM2>>>(nullptr, bimg2, b2, out);  // 9
}

// round 13
// speedup vs baseline: 1.4542x; 1.4044x over previous
#include <cuda_runtime.h>
#include <cuda_fp16.h>
#include <cuda_pipeline.h>
#include <mma.h>
#include <cstdint>

using namespace nvcuda;

#define NN 100000
#define NE 1600000
#define SCAN_B 1024
#define NBLK ((NN + SCAN_B - 1) / SCAN_B)   // 98

// ---------------- scratch (device globals; no allocation allowed) ----------------
__device__ __align__(16) float g_aggr[(size_t)NN * 128];
__device__ __align__(16) float g_h[(size_t)NN * 128];
__device__ int g_deg[NN];                   // zeroed by scan1 right after it reads
__device__ int g_rowStart[NN + 1];
__device__ int g_cursor[NN];
__device__ int g_srcIdx[NE];
__device__ int g_blockTot[NBLK];
// fp16 weight images: [half][k 0..127][n 0..NP)
__device__ __align__(16) unsigned short g_Bimg1[2 * 128 * 136];  // layer1 NP=136
__device__ __align__(16) unsigned short g_Bimg2[2 * 128 * 72];   // layer2 NP=72

// split one float pair into packed fp16 hi and lo words (hi+lo ~exact to 2^-22)
__device__ __forceinline__ void split2h(float a, float b, uint32_t& h, uint32_t& l) {
    __half2 hb = __floats2half2_rn(a, b);
    float2 hf = __half22float2(hb);
    __half2 lb = __floats2half2_rn(a - hf.x, b - hf.y);
    h = *reinterpret_cast<uint32_t*>(&hb);
    l = *reinterpret_cast<uint32_t*>(&lb);
}

// ---------------- CSR build (ordered scan -- the measured-fast scheme) ----------------
__global__ void k_count(const int* __restrict__ edst) {
    int i = blockIdx.x * blockDim.x + threadIdx.x;
    if (i < NE) atomicAdd(&g_deg[edst[i]], 1);
}
__global__ void __launch_bounds__(SCAN_B) k_scan1() {
    __shared__ int s[SCAN_B];
    int t = threadIdx.x;
    int i = blockIdx.x * SCAN_B + t;
    int v = (i < NN) ? g_deg[i] : 0;
    if (i < NN) g_deg[i] = 0;               // restore invariant for next call (only reader is this kernel)
    s[t] = v;
    __syncthreads();
#pragma unroll
    for (int off = 1; off < SCAN_B; off <<= 1) {
        int x = (t >= off) ? s[t - off] : 0;
        __syncthreads();
        s[t] += x;
        __syncthreads();
    }
    if (i < NN) g_rowStart[i] = s[t] - v;
    if (t == SCAN_B - 1) g_blockTot[blockIdx.x] = s[t];
}
__global__ void k_scan2() {
    __shared__ int s[128];
    int t = threadIdx.x;
    int v = (t < NBLK) ? g_blockTot[t] : 0;
    s[t] = v;
    __syncthreads();
#pragma unroll
    for (int off = 1; off < 128; off <<= 1) {
        int x = (t >= off) ? s[t - off] : 0;
        __syncthreads();
        s[t] += x;
        __syncthreads();
    }
    if (t < NBLK) g_blockTot[t] = s[t] - v;
}
__global__ void __launch_bounds__(SCAN_B) k_scan3() {
    int i = blockIdx.x * SCAN_B + threadIdx.x;
    if (i < NN) {
        int r = g_rowStart[i] + g_blockTot[blockIdx.x];
        g_rowStart[i] = r;
        g_cursor[i] = r;
    }
    if (i == 0) g_rowStart[NN] = NE;
}
__global__ void k_fill(const int* __restrict__ esrc, const int* __restrict__ edst) {
    int i = blockIdx.x * blockDim.x + threadIdx.x;
    if (i < NE) {
        int p = atomicAdd(&g_cursor[edst[i]], 1);
        g_srcIdx[p] = esrc[i];
    }
}

// ---------------- aggregation: warp per node, gather-max over CSR row (R10 form) ----------
__device__ __forceinline__ float4 max4(float4 a, float4 b) {
    return make_float4(fmaxf(a.x, b.x), fmaxf(a.y, b.y), fmaxf(a.z, b.z), fmaxf(a.w, b.w));
}
template<bool USE_H>
__global__ void __launch_bounds__(256) k_aggr(const float* __restrict__ xin) {
    int w = (blockIdx.x * blockDim.x + threadIdx.x) >> 5;
    if (w >= NN) return;
    int lane = threadIdx.x & 31;
    const float* feat = USE_H ? g_h : xin;
    int beg = g_rowStart[w];
    int end = g_rowStart[w + 1];
    const float NEG = __int_as_float(0xff800000);
    float4 m = make_float4(NEG, NEG, NEG, NEG);
    int e = beg;
    for (; e + 4 <= end; e += 4) {
        int s0 = g_srcIdx[e + 0], s1 = g_srcIdx[e + 1];
        int s2 = g_srcIdx[e + 2], s3 = g_srcIdx[e + 3];
        float4 v0 = *(const float4*)(feat + (size_t)s0 * 128 + lane * 4);
        float4 v1 = *(const float4*)(feat + (size_t)s1 * 128 + lane * 4);
        float4 v2 = *(const float4*)(feat + (size_t)s2 * 128 + lane * 4);
        float4 v3 = *(const float4*)(feat + (size_t)s3 * 128 + lane * 4);
        m = max4(m, max4(max4(v0, v1), max4(v2, v3)));
    }
    for (; e < end; e++) {
        float4 v0 = *(const float4*)(feat + (size_t)g_srcIdx[e] * 128 + lane * 4);
        m = max4(m, v0);
    }
    if (beg == end) m = make_float4(0.f, 0.f, 0.f, 0.f);
    *(float4*)(g_aggr + (size_t)w * 128 + lane * 4) = m;
}

// ---------------- weight prep: single fp16 B[k][n] image per half ----------------
template<int COUT>
__global__ void k_prepB(const float* __restrict__ Wl, const float* __restrict__ Wr,
                        unsigned short* __restrict__ dst) {
    constexpr int NP = COUT + 8;
    int idx = blockIdx.x * blockDim.x + threadIdx.x;
    if (idx >= 2 * 128 * COUT) return;
    int half = idx / (128 * COUT);
    int rem = idx - half * 128 * COUT;
    int k = rem / COUT;
    int n = rem - k * COUT;
    float f = (half ? Wr : Wl)[k * COUT + n];
    __half hb = __float2half_rn(f);
    dst[((size_t)half * 128 + k) * NP + n] = *reinterpret_cast<unsigned short*>(&hb);
}

// ---------------- wmma fp16 2-term fused SAGE GEMM (R10 winner + cp.async B) ----------
// CTA = 64 rows x COUT, 8 warps in 2(m) x 4(n), warp tile 32 x COUT/4. 3-4 CTAs/SM.
// A split into fp16 hi+lo during staging; B single fp16 image. Terms: AhB + AlB.
template<int COUT, bool L1>
__global__ void __launch_bounds__(256) k_gemm_wm(const float* __restrict__ xin,
                                                 const unsigned short* __restrict__ Bimg,
                                                 const float* __restrict__ bias,
                                                 float* __restrict__ outp) {
    constexpr int BM = 64;
    constexpr int NP = COUT + 8;
    constexpr int AP = 136;
    constexpr int WN = COUT / 4;            // L1:32, L2:16
    constexpr int NT = WN / 16;             // L1:2,  L2:1
    constexpr int EW = WN + 4;
    extern __shared__ char smem[];
    __half* Ah = (__half*)smem;
    __half* Al = Ah + BM * AP;
    __half* Bs = Al + BM * AP;              // current half image: 128 x NP

    int tid = threadIdx.x, wid = tid >> 5, lane = tid & 31;
    int wm = wid & 1, wn = wid >> 1;
    int rowBase = blockIdx.x * BM;

    wmma::fragment<wmma::accumulator, 16, 16, 16, float> acc[2][NT];
#pragma unroll
    for (int i = 0; i < 2; i++)
#pragma unroll
        for (int j = 0; j < NT; j++) wmma::fill_fragment(acc[i][j], 0.0f);

    const float* rootSrc = L1 ? xin : g_h;
    int r = tid >> 2, kq = (tid & 3) << 5;
    int grow = rowBase + r;

    for (int half = 0; half < 2; half++) {
        // kick off B copy asynchronously -- overlaps with A staging below
        {
            const char* src = (const char*)(Bimg + (size_t)half * 128 * NP);
            const int n4 = 128 * NP * 2 / 16;
            for (int i = tid; i < n4; i += 256)
                __pipeline_memcpy_async((char*)Bs + i * 16, src + i * 16, 16);
            __pipeline_commit();
        }
        // stage A half: thread covers row r, k in [kq, kq+32), split to hi/lo fp16
        const float* Asrc = half ? rootSrc : g_aggr;
        const float4* srcv = (grow < NN) ? (const float4*)(Asrc + (size_t)grow * 128 + kq) : nullptr;
#pragma unroll
        for (int i = 0; i < 8; i++) {
            float4 v = srcv ? srcv[i] : make_float4(0.f, 0.f, 0.f, 0.f);
            uint32_t h0, l0, h1, l1;
            split2h(v.x, v.y, h0, l0);
            split2h(v.z, v.w, h1, l1);
            *(uint2*)((unsigned short*)Ah + (size_t)r * AP + kq + i * 4) = make_uint2(h0, h1);
            *(uint2*)((unsigned short*)Al + (size_t)r * AP + kq + i * 4) = make_uint2(l0, l1);
        }
        __pipeline_wait_prior(0);
        __syncthreads();

#pragma unroll
        for (int ks = 0; ks < 8; ks++) {
            int k0 = ks * 16;
            wmma::fragment<wmma::matrix_a, 16, 16, 16, __half, wmma::row_major> fa_h[2], fa_l[2];
#pragma unroll
            for (int mt = 0; mt < 2; mt++) {
                wmma::load_matrix_sync(fa_h[mt], Ah + (size_t)(wm * 32 + mt * 16) * AP + k0, AP);
                wmma::load_matrix_sync(fa_l[mt], Al + (size_t)(wm * 32 + mt * 16) * AP + k0, AP);
            }
#pragma unroll
            for (int nt = 0; nt < NT; nt++) {
                wmma::fragment<wmma::matrix_b, 16, 16, 16, __half, wmma::row_major> fb;
                wmma::load_matrix_sync(fb, Bs + (size_t)k0 * NP + wn * WN + nt * 16, NP);
#pragma unroll
                for (int mt = 0; mt < 2; mt++) wmma::mma_sync(acc[mt][nt], fa_h[mt], fb, acc[mt][nt]);
#pragma unroll
                for (int mt = 0; mt < 2; mt++) wmma::mma_sync(acc[mt][nt], fa_l[mt], fb, acc[mt][nt]);
            }
        }
        __syncthreads();
    }

    // ---- epilogue: bounce fragments through smem, fuse bias+ReLU ----
    float* bw = (float*)Ah + (size_t)wid * 32 * EW;
#pragma unroll
    for (int mt = 0; mt < 2; mt++)
#pragma unroll
        for (int nt = 0; nt < NT; nt++)
            wmma::store_matrix_sync(bw + mt * 16 * EW + nt * 16, acc[mt][nt], EW, wmma::mem_row_major);
    __syncwarp();

    int orow = rowBase + wm * 32 + lane;
    float* out = L1 ? g_h : outp;
    if (orow < NN) {
        float* op = out + (size_t)orow * COUT + wn * WN;
        const float* br = bw + (size_t)lane * EW;
#pragma unroll
        for (int c = 0; c < WN; c += 4) {
            float4 v = make_float4(br[c], br[c + 1], br[c + 2], br[c + 3]);
            v.x += bias[wn * WN + c + 0];
            v.y += bias[wn * WN + c + 1];
            v.z += bias[wn * WN + c + 2];
            v.w += bias[wn * WN + c + 3];
            if (L1) {
                v.x = fmaxf(v.x, 0.f); v.y = fmaxf(v.y, 0.f);
                v.z = fmaxf(v.z, 0.f); v.w = fmaxf(v.w, 0.f);
            }
            *(float4*)(op + c) = v;
        }
    }
}

extern "C" void kernel_launch(void* const* d_in, const int* in_sizes, int n_in,
                              void* d_out, int out_size) {
    const float* x   = (const float*)d_in[0];
    const int*   ei  = (const int*)d_in[1];
    const float* W1l = (const float*)d_in[2];
    const float* b1  = (const float*)d_in[3];
    const float* W1r = (const float*)d_in[4];
    const float* W2l = (const float*)d_in[5];
    const float* b2  = (const float*)d_in[6];
    const float* W2r = (const float*)d_in[7];
    float*       out = (float*)d_out;

    const int* esrc = ei;
    const int* edst = ei + NE;

    const int edgeBlocks = (NE + 255) / 256;
    const int aggrBlocks = (NN * 32 + 255) / 256;
    const int gemmBlocks = (NN + 63) / 64;              // 1563

    // dynamic SMEM: A(2 x 64 x 136) + B(128 x NP), fp16  -- same as winning R10
    const int SMEM1 = (2 * 64 * 136 + 128 * 136) * 2;   // 69,632 -> 3 CTAs/SM
    const int SMEM2 = (2 * 64 * 136 + 128 * 72) * 2;    // 53,248 -> 4 CTAs/SM
    cudaFuncSetAttribute(k_gemm_wm<128, true>, cudaFuncAttributeMaxDynamicSharedMemorySize, SMEM1);
    cudaFuncSetAttribute(k_gemm_wm<64, false>, cudaFuncAttributeMaxDynamicSharedMemorySize, SMEM2);

    unsigned short *bimg1, *bimg2;
    cudaGetSymbolAddress((void**)&bimg1, g_Bimg1);
    cudaGetSymbolAddress((void**)&bimg2, g_Bimg2);

    // CSR build (ordered scan; g_deg re-zeroed inside scan1 right after its read)
    k_count<<<edgeBlocks, 256>>>(edst);
    k_scan1<<<NBLK, SCAN_B>>>();
    k_scan2<<<1, 128>>>();
    k_scan3<<<NBLK, SCAN_B>>>();
    k_fill<<<edgeBlocks, 256>>>(esrc, edst);

    // weight prep
    k_prepB<128><<<(2 * 128 * 128 + 255) / 256, 256>>>(W1l, W1r, bimg1);
    k_prepB<64><<<(2 * 128 * 64 + 255) / 256, 256>>>(W2l, W2r, bimg2);

    // Layer 1
    k_aggr<false><<<aggrBlocks, 256>>>(x);
    k_gemm_wm<128, true><<<gemmBlocks, 256, SMEM1>>>(x, bimg1, b1, nullptr);

    // Layer 2
    k_aggr<true><<<aggrBlocks, 256>>>(nullptr);
    k_gemm_wm<64, false><<<gemmBlocks, 256, SMEM2>>>(nullptr, bimg2, b2, out);
}